// round 5
// baseline (speedup 1.0000x reference)
#include <cuda_runtime.h>
#include <math.h>

#define BN 8
#define TN 8192
#define WDN 128
#define SDN 512
#define FOUT 6145
#define SKIP0 2047   /* 8192 - 6145 */
#define TT 32

// Scratch (static device globals; no runtime allocation)
__device__ float g_xA[(size_t)BN * WDN * TN];
__device__ float g_xB[(size_t)BN * WDN * TN];
__device__ float g_skip[(size_t)BN * SDN * FOUT];
__device__ float g_h1[(size_t)BN * SDN * FOUT];

__global__ void zero_kernel(float* __restrict__ p, int n) {
    for (int i = blockIdx.x * blockDim.x + threadIdx.x; i < n;
         i += gridDim.x * blockDim.x)
        p[i] = 0.f;
}

// x[b][c][t] = emb[y[b][t]][c]
__global__ void embed_kernel(const int* __restrict__ y,
                             const float* __restrict__ emb,
                             float* __restrict__ x) {
    const int total = BN * WDN * TN;  // 2^23
    for (int i = blockIdx.x * blockDim.x + threadIdx.x; i < total;
         i += gridDim.x * blockDim.x) {
        int t = i & (TN - 1);
        int c = (i >> 13) & (WDN - 1);
        int b = i >> 20;
        x[i] = emb[y[b * TN + t] * WDN + c];
    }
}

// Fused per-layer kernel: dilated conv (K=2) -> gated tanh*sigmoid ->
// residual 128x128 GEMM (writes x_next) -> skip 128x512 GEMM (accumulates).
// Absolute time indexing: x_i valid for t in [off, TN). Output t in
// [off+d, TN) uses x[t-d] (tap h=0) and x[t] (tap h=1).
__global__ void __launch_bounds__(256)
layer_kernel(const float* __restrict__ xin,
             float* __restrict__ xout,
             float* __restrict__ skip,
             const float* __restrict__ Wd,
             const float* __restrict__ bd,
             const float* __restrict__ Wr,
             const float* __restrict__ br,
             const float* __restrict__ Ws,
             const float* __restrict__ bs,
             int d, int tstart) {
    extern __shared__ float sm[];
    float* sDel = sm;                 // [128][32]  x[t-d]
    float* sCur = sm + WDN * TT;      // [128][32]  x[t]
    float* sIn  = sm + 2 * WDN * TT;  // [256][32]  in_act, later res staging
    float* sAct = sm + 4 * WDN * TT;  // [128][32]  gated acts
    // skip staging overlays sm[0 .. 512*32)

    const int b   = blockIdx.y;
    const int t0  = tstart + blockIdx.x * TT;
    const int tid = threadIdx.x;
    const float* xb = xin + (size_t)b * WDN * TN;

    // 1. load tiles (coalesced in t)
    for (int i = tid; i < WDN * TT; i += 256) {
        int c = i >> 5, tt = i & 31;
        int t = t0 + tt;
        float vc = 0.f, vd = 0.f;
        if (t < TN) {
            vc = xb[c * TN + t];
            vd = xb[c * TN + t - d];
        }
        sCur[i] = vc;
        sDel[i] = vd;
    }
    __syncthreads();

    // 2. conv: thread owns output channel o = tid (0..255), all 32 t's
    {
        float acc[TT];
#pragma unroll
        for (int k = 0; k < TT; k++) acc[k] = 0.f;
        const int o = tid;
        for (int c = 0; c < WDN; c++) {
            float w0 = Wd[c * 256 + o];              // h=0 tap: x[t-d]
            float w1 = Wd[(WDN + c) * 256 + o];      // h=1 tap: x[t]
            const float4* v0 = reinterpret_cast<const float4*>(sDel + c * TT);
            const float4* v1 = reinterpret_cast<const float4*>(sCur + c * TT);
#pragma unroll
            for (int k = 0; k < TT / 4; k++) {
                float4 a = v0[k];
                float4 q = v1[k];
                acc[4*k+0] = fmaf(w0, a.x, acc[4*k+0]);
                acc[4*k+1] = fmaf(w0, a.y, acc[4*k+1]);
                acc[4*k+2] = fmaf(w0, a.z, acc[4*k+2]);
                acc[4*k+3] = fmaf(w0, a.w, acc[4*k+3]);
                acc[4*k+0] = fmaf(w1, q.x, acc[4*k+0]);
                acc[4*k+1] = fmaf(w1, q.y, acc[4*k+1]);
                acc[4*k+2] = fmaf(w1, q.z, acc[4*k+2]);
                acc[4*k+3] = fmaf(w1, q.w, acc[4*k+3]);
            }
        }
        float bias = bd[o];
#pragma unroll
        for (int k = 0; k < TT; k++) sIn[o * TT + k] = acc[k] + bias;
    }
    __syncthreads();

    // 3. gated activation -> sAct
    for (int i = tid; i < WDN * TT; i += 256) {
        int c = i >> 5, tt = i & 31;
        float a = sIn[c * TT + tt];
        float g = sIn[(c + WDN) * TT + tt];
        sAct[i] = tanhf(a) * (1.f / (1.f + expf(-g)));
    }
    __syncthreads();

    // 4. residual GEMM: 128 outs x 32 t; thread = (r = tid&127, half = tid>>7)
    {
        const int r = tid & (WDN - 1);
        const int tb = (tid >> 7) * 16;
        float acc[16];
#pragma unroll
        for (int k = 0; k < 16; k++) acc[k] = 0.f;
        for (int c = 0; c < WDN; c++) {
            float w = Wr[c * WDN + r];
            const float4* v = reinterpret_cast<const float4*>(sAct + c * TT + tb);
#pragma unroll
            for (int k = 0; k < 4; k++) {
                float4 a = v[k];
                acc[4*k+0] = fmaf(w, a.x, acc[4*k+0]);
                acc[4*k+1] = fmaf(w, a.y, acc[4*k+1]);
                acc[4*k+2] = fmaf(w, a.z, acc[4*k+2]);
                acc[4*k+3] = fmaf(w, a.w, acc[4*k+3]);
            }
        }
        float bias = br[r];
#pragma unroll
        for (int k = 0; k < 16; k++)
            sIn[r * TT + tb + k] = acc[k] + bias + sCur[r * TT + tb + k];
    }
    __syncthreads();

    // 5. write x_next (coalesced)
    {
        float* xob = xout + (size_t)b * WDN * TN;
        for (int i = tid; i < WDN * TT; i += 256) {
            int c = i >> 5, tt = i & 31;
            int t = t0 + tt;
            if (t < TN) xob[c * TN + t] = sIn[i];
        }
    }
    __syncthreads();

    // 6. skip GEMM (only if tile intersects t >= SKIP0)
    if (t0 + TT > SKIP0) {
        for (int g = 0; g < 2; g++) {
            int s = tid + g * 256;
            float acc[TT];
#pragma unroll
            for (int k = 0; k < TT; k++) acc[k] = 0.f;
            for (int c = 0; c < WDN; c++) {
                float w = Ws[c * SDN + s];
                const float4* v = reinterpret_cast<const float4*>(sAct + c * TT);
#pragma unroll
                for (int k = 0; k < TT / 4; k++) {
                    float4 a = v[k];
                    acc[4*k+0] = fmaf(w, a.x, acc[4*k+0]);
                    acc[4*k+1] = fmaf(w, a.y, acc[4*k+1]);
                    acc[4*k+2] = fmaf(w, a.z, acc[4*k+2]);
                    acc[4*k+3] = fmaf(w, a.w, acc[4*k+3]);
                }
            }
            float bias = bs[s];
#pragma unroll
            for (int k = 0; k < TT; k++) sm[s * TT + k] = acc[k] + bias;
        }
        __syncthreads();
        float* skb = skip + (size_t)b * SDN * FOUT;
        for (int i = tid; i < SDN * TT; i += 256) {
            int s = i >> 5, tt = i & 31;
            int t = t0 + tt;
            if (t >= SKIP0 && t < TN)
                skb[(size_t)s * FOUT + (t - SKIP0)] += sm[i];
        }
    }
}

// h1[b][o][j] = relu( sum_c relu(skip[b][c][j]) * W[c*512+o] )
__global__ void __launch_bounds__(256)
post1_kernel(const float* __restrict__ skip,
             float* __restrict__ h1,
             const float* __restrict__ W) {
    extern __shared__ float sm[];
    float* tile = sm;             // [512][32]
    float* stg  = sm + SDN * TT;  // [256][32]
    const int b = blockIdx.y;
    const int j0 = blockIdx.x * TT;
    const int tid = threadIdx.x;

    const float* sp = skip + (size_t)b * SDN * FOUT;
    for (int i = tid; i < SDN * TT; i += 256) {
        int c = i >> 5, tt = i & 31;
        int j = j0 + tt;
        float v = 0.f;
        if (j < FOUT) v = sp[(size_t)c * FOUT + j];
        tile[i] = fmaxf(v, 0.f);
    }
    __syncthreads();

    float* hp = h1 + (size_t)b * SDN * FOUT;
    for (int g = 0; g < 2; g++) {
        int o = tid + g * 256;
        float acc[TT];
#pragma unroll
        for (int k = 0; k < TT; k++) acc[k] = 0.f;
        for (int c = 0; c < SDN; c++) {
            float w = W[c * SDN + o];
            const float4* v = reinterpret_cast<const float4*>(tile + c * TT);
#pragma unroll
            for (int k = 0; k < TT / 4; k++) {
                float4 a = v[k];
                acc[4*k+0] = fmaf(w, a.x, acc[4*k+0]);
                acc[4*k+1] = fmaf(w, a.y, acc[4*k+1]);
                acc[4*k+2] = fmaf(w, a.z, acc[4*k+2]);
                acc[4*k+3] = fmaf(w, a.w, acc[4*k+3]);
            }
        }
#pragma unroll
        for (int k = 0; k < TT; k++) stg[tid * TT + k] = fmaxf(acc[k], 0.f);
        __syncthreads();
        for (int i = tid; i < 256 * TT; i += 256) {
            int oo = (i >> 5) + g * 256, tt = i & 31;
            int j = j0 + tt;
            if (j < FOUT) hp[(size_t)oo * FOUT + j] = stg[i];
        }
        __syncthreads();
    }
}

// out[b][o][j] = sum_c h1[b][c][j] * W[c*256+o]
__global__ void __launch_bounds__(256)
post2_kernel(const float* __restrict__ h1,
             float* __restrict__ out,
             const float* __restrict__ W) {
    extern __shared__ float sm[];
    float* tile = sm;             // [512][32]
    float* stg  = sm + SDN * TT;  // [256][32]
    const int b = blockIdx.y;
    const int j0 = blockIdx.x * TT;
    const int tid = threadIdx.x;

    const float* hp = h1 + (size_t)b * SDN * FOUT;
    for (int i = tid; i < SDN * TT; i += 256) {
        int c = i >> 5, tt = i & 31;
        int j = j0 + tt;
        tile[i] = (j < FOUT) ? hp[(size_t)c * FOUT + j] : 0.f;
    }
    __syncthreads();

    {
        int o = tid;
        float acc[TT];
#pragma unroll
        for (int k = 0; k < TT; k++) acc[k] = 0.f;
        for (int c = 0; c < SDN; c++) {
            float w = W[c * 256 + o];
            const float4* v = reinterpret_cast<const float4*>(tile + c * TT);
#pragma unroll
            for (int k = 0; k < TT / 4; k++) {
                float4 a = v[k];
                acc[4*k+0] = fmaf(w, a.x, acc[4*k+0]);
                acc[4*k+1] = fmaf(w, a.y, acc[4*k+1]);
                acc[4*k+2] = fmaf(w, a.z, acc[4*k+2]);
                acc[4*k+3] = fmaf(w, a.w, acc[4*k+3]);
            }
        }
#pragma unroll
        for (int k = 0; k < TT; k++) stg[tid * TT + k] = acc[k];
    }
    __syncthreads();
    float* ob = out + (size_t)b * 256 * FOUT;
    for (int i = tid; i < 256 * TT; i += 256) {
        int oo = i >> 5, tt = i & 31;
        int j = j0 + tt;
        if (j < FOUT) ob[(size_t)oo * FOUT + j] = stg[i];
    }
}

extern "C" void kernel_launch(void* const* d_in, const int* in_sizes, int n_in,
                              void* d_out, int out_size) {
    const int*   y   = (const int*)d_in[0];
    const float* emb = (const float*)d_in[1];
    const float* Wd  = (const float*)d_in[2];
    const float* bd  = (const float*)d_in[3];
    const float* Wr  = (const float*)d_in[4];
    const float* br  = (const float*)d_in[5];
    const float* Ws  = (const float*)d_in[6];
    const float* bs  = (const float*)d_in[7];
    const float* p1  = (const float*)d_in[8];
    const float* p2  = (const float*)d_in[9];
    float* out = (float*)d_out;

    float *xA, *xB, *skip, *h1;
    cudaGetSymbolAddress((void**)&xA,   g_xA);
    cudaGetSymbolAddress((void**)&xB,   g_xB);
    cudaGetSymbolAddress((void**)&skip, g_skip);
    cudaGetSymbolAddress((void**)&h1,   g_h1);

    const int layerSmem = 5 * WDN * TT * 4;            // 80 KB
    const int postSmem  = (SDN * TT + 256 * TT) * 4;   // 96 KB
    cudaFuncSetAttribute(layer_kernel, cudaFuncAttributeMaxDynamicSharedMemorySize, layerSmem);
    cudaFuncSetAttribute(post1_kernel, cudaFuncAttributeMaxDynamicSharedMemorySize, postSmem);
    cudaFuncSetAttribute(post2_kernel, cudaFuncAttributeMaxDynamicSharedMemorySize, postSmem);

    zero_kernel<<<512, 256>>>(skip, BN * SDN * FOUT);
    embed_kernel<<<2048, 256>>>(y, emb, xA);

    static const int dil[20] = {1, 2, 4, 8, 16, 32, 64, 128, 256, 512,
                                1, 2, 4, 8, 16, 32, 64, 128, 256, 512};
    int off = 0;
    float* cur = xA;
    float* nxt = xB;
    for (int i = 0; i < 20; i++) {
        int d = dil[i];
        int tstart = off + d;
        int len = TN - tstart;
        int tiles = (len + TT - 1) / TT;
        layer_kernel<<<dim3(tiles, BN), 256, layerSmem>>>(
            cur, nxt, skip,
            Wd + (size_t)i * 2 * WDN * (2 * WDN),
            bd + (size_t)i * 2 * WDN,
            Wr + (size_t)i * WDN * WDN,
            br + (size_t)i * WDN,
            Ws + (size_t)i * WDN * SDN,
            bs + (size_t)i * SDN,
            d, tstart);
        float* tmp = cur; cur = nxt; nxt = tmp;
        off += d;
    }

    int jt = (FOUT + TT - 1) / TT;  // 193
    post1_kernel<<<dim3(jt, BN), 256, postSmem>>>(skip, h1, p1);
    post2_kernel<<<dim3(jt, BN), 256, postSmem>>>(h1, out, p2);
}

// round 14
// speedup vs baseline: 1.4472x; 1.4472x over previous
#include <cuda_runtime.h>
#include <math.h>

#define BN 8
#define TN 8192
#define WDN 128
#define SDN 512
#define FOUT 6145
#define SKIP0 2047   /* 8192 - 6145 */
#define TT 32
#define XS 36        /* padded stride for sDel/sCur/sAct (float4-aligned, conflict-light) */
#define CS 33        /* padded stride for staging (conflict-free) */

// Scratch (static device globals; no runtime allocation)
__device__ float g_xA[(size_t)BN * WDN * TN];
__device__ float g_xB[(size_t)BN * WDN * TN];
__device__ float g_skip[(size_t)BN * SDN * FOUT];
__device__ float g_h1[(size_t)BN * SDN * FOUT];

__device__ __forceinline__ float fast_tanh(float a) {
    float e = __expf(2.f * a);
    return 1.f - 2.f / (e + 1.f);
}
__device__ __forceinline__ float fast_sig(float g) {
    return 1.f / (1.f + __expf(-g));
}

__global__ void zero_kernel(float* __restrict__ p, int n) {
    for (int i = blockIdx.x * blockDim.x + threadIdx.x; i < n;
         i += gridDim.x * blockDim.x)
        p[i] = 0.f;
}

// x[b][c][t] = emb[y[b][t]][c]
__global__ void embed_kernel(const int* __restrict__ y,
                             const float* __restrict__ emb,
                             float* __restrict__ x) {
    const int total = BN * WDN * TN;  // 2^23
    for (int i = blockIdx.x * blockDim.x + threadIdx.x; i < total;
         i += gridDim.x * blockDim.x) {
        int t = i & (TN - 1);
        int c = (i >> 13) & (WDN - 1);
        int b = i >> 20;
        x[i] = emb[y[b * TN + t] * WDN + c];
    }
}

// Fused per-layer kernel. smem = 3 tiles * 128 * XS floats = 54KB -> 4 CTAs/SM.
__global__ void __launch_bounds__(256, 4)
layer_kernel(const float* __restrict__ xin,
             float* __restrict__ xout,
             float* __restrict__ skip,
             const float* __restrict__ Wd,
             const float* __restrict__ bd,
             const float* __restrict__ Wr,
             const float* __restrict__ br,
             const float* __restrict__ Ws,
             const float* __restrict__ bs,
             int d, int tstart) {
    extern __shared__ float sm[];
    float* sDel = sm;                  // [128][XS]  x[t-d]
    float* sCur = sm + 128 * XS;       // [128][XS]  x[t]
    float* sAct = sm + 2 * 128 * XS;   // [128][XS]  gated acts
    // resStage overlays sDel ([128][CS]); skip chunk overlays sDel+sCur ([256][CS])

    const int b   = blockIdx.y;
    const int t0  = tstart + blockIdx.x * TT;
    const int tid = threadIdx.x;
    const float* xb = xin + (size_t)b * WDN * TN;

    // 1. load tiles (coalesced in t; conflict-free STS)
    for (int i = tid; i < WDN * TT; i += 256) {
        int c = i >> 5, tt = i & 31;
        int t = t0 + tt;
        float vc = 0.f, vd = 0.f;
        if (t < TN) {
            vc = xb[c * TN + t];
            vd = xb[c * TN + t - d];
        }
        sCur[c * XS + tt] = vc;
        sDel[c * XS + tt] = vd;
    }
    __syncthreads();

    // 2. conv + gate fused: thread owns output pair (o, o+128), 16 t's.
    {
        const int o  = tid & 127;
        const int th = (tid >> 7) * 16;
        float aA[16], aG[16];
#pragma unroll
        for (int k = 0; k < 16; k++) { aA[k] = 0.f; aG[k] = 0.f; }
        const float* WdA = Wd + o;
#pragma unroll 2
        for (int c = 0; c < WDN; c++) {
            float w0a = WdA[c * 256];                // tap h=0 (x[t-d]), out o
            float w1a = WdA[(WDN + c) * 256];        // tap h=1 (x[t]),   out o
            float w0g = WdA[c * 256 + 128];          // out o+128
            float w1g = WdA[(WDN + c) * 256 + 128];
            const float4* v0 = reinterpret_cast<const float4*>(sDel + c * XS + th);
            const float4* v1 = reinterpret_cast<const float4*>(sCur + c * XS + th);
#pragma unroll
            for (int k = 0; k < 4; k++) {
                float4 a = v0[k];
                float4 q = v1[k];
                aA[4*k+0] = fmaf(w0a, a.x, aA[4*k+0]); aA[4*k+0] = fmaf(w1a, q.x, aA[4*k+0]);
                aA[4*k+1] = fmaf(w0a, a.y, aA[4*k+1]); aA[4*k+1] = fmaf(w1a, q.y, aA[4*k+1]);
                aA[4*k+2] = fmaf(w0a, a.z, aA[4*k+2]); aA[4*k+2] = fmaf(w1a, q.z, aA[4*k+2]);
                aA[4*k+3] = fmaf(w0a, a.w, aA[4*k+3]); aA[4*k+3] = fmaf(w1a, q.w, aA[4*k+3]);
                aG[4*k+0] = fmaf(w0g, a.x, aG[4*k+0]); aG[4*k+0] = fmaf(w1g, q.x, aG[4*k+0]);
                aG[4*k+1] = fmaf(w0g, a.y, aG[4*k+1]); aG[4*k+1] = fmaf(w1g, q.y, aG[4*k+1]);
                aG[4*k+2] = fmaf(w0g, a.z, aG[4*k+2]); aG[4*k+2] = fmaf(w1g, q.z, aG[4*k+2]);
                aG[4*k+3] = fmaf(w0g, a.w, aG[4*k+3]); aG[4*k+3] = fmaf(w1g, q.w, aG[4*k+3]);
            }
        }
        float ba = bd[o], bg = bd[o + 128];
#pragma unroll
        for (int j = 0; j < 16; j++) {
            float av = aA[j] + ba;
            float gv = aG[j] + bg;
            sAct[o * XS + th + j] = fast_tanh(av) * fast_sig(gv);
        }
    }
    __syncthreads();   // sAct ready; all conv reads of sDel done

    // 3. residual GEMM -> resStage (overlays sDel, stride CS)
    {
        const int r  = tid & 127;
        const int tb = (tid >> 7) * 16;
        float acc[16];
#pragma unroll
        for (int k = 0; k < 16; k++) acc[k] = 0.f;
        const float* WrR = Wr + r;
#pragma unroll 2
        for (int c = 0; c < WDN; c++) {
            float w = WrR[c * WDN];
            const float4* v = reinterpret_cast<const float4*>(sAct + c * XS + tb);
#pragma unroll
            for (int k = 0; k < 4; k++) {
                float4 a = v[k];
                acc[4*k+0] = fmaf(w, a.x, acc[4*k+0]);
                acc[4*k+1] = fmaf(w, a.y, acc[4*k+1]);
                acc[4*k+2] = fmaf(w, a.z, acc[4*k+2]);
                acc[4*k+3] = fmaf(w, a.w, acc[4*k+3]);
            }
        }
        float* resStage = sDel;
        float bias = br[r];
#pragma unroll
        for (int j = 0; j < 16; j++)
            resStage[r * CS + tb + j] = acc[j] + bias + sCur[r * XS + tb + j];
    }
    __syncthreads();

    // 4. write x_next (coalesced from resStage)
    {
        float* xob = xout + (size_t)b * WDN * TN;
        const float* resStage = sDel;
        for (int i = tid; i < WDN * TT; i += 256) {
            int c = i >> 5, tt = i & 31;
            int t = t0 + tt;
            if (t < TN) xob[c * TN + t] = resStage[c * CS + tt];
        }
    }

    // 5. skip GEMM in two 256-row passes, staged over sDel+sCur region
    if (t0 + TT > SKIP0) {
        float* chunk = sm;  // [256][CS]
        float* skb = skip + (size_t)b * SDN * FOUT;
#pragma unroll 1
        for (int p = 0; p < 2; p++) {
            __syncthreads();   // protect region reuse (copy-out / prev RMW reads)
            const int s = p * 256 + tid;
            float acc[TT];
#pragma unroll
            for (int k = 0; k < TT; k++) acc[k] = 0.f;
            const float* WsS = Ws + s;
#pragma unroll 2
            for (int c = 0; c < WDN; c++) {
                float w = WsS[c * SDN];
                const float4* v = reinterpret_cast<const float4*>(sAct + c * XS);
#pragma unroll
                for (int k = 0; k < TT / 4; k++) {
                    float4 a = v[k];
                    acc[4*k+0] = fmaf(w, a.x, acc[4*k+0]);
                    acc[4*k+1] = fmaf(w, a.y, acc[4*k+1]);
                    acc[4*k+2] = fmaf(w, a.z, acc[4*k+2]);
                    acc[4*k+3] = fmaf(w, a.w, acc[4*k+3]);
                }
            }
            float bias = bs[s];
#pragma unroll
            for (int k = 0; k < TT; k++) chunk[tid * CS + k] = acc[k] + bias;
            __syncthreads();
            // coalesced RMW into skip
            for (int i = tid; i < 256 * TT; i += 256) {
                int row = i >> 5, col = i & 31;
                int t = t0 + col;
                if (t >= SKIP0 && t < TN)
                    skb[(size_t)(p * 256 + row) * FOUT + (t - SKIP0)] += chunk[row * CS + col];
            }
        }
    }
}

// h1[b][o][j] = relu( sum_c relu(skip[b][c][j]) * W[c*512+o] )
__global__ void __launch_bounds__(256)
post1_kernel(const float* __restrict__ skip,
             float* __restrict__ h1,
             const float* __restrict__ W) {
    extern __shared__ float sm[];
    float* tile = sm;             // [512][32]
    float* stg  = sm + SDN * TT;  // [256][32]
    const int b = blockIdx.y;
    const int j0 = blockIdx.x * TT;
    const int tid = threadIdx.x;

    const float* sp = skip + (size_t)b * SDN * FOUT;
    for (int i = tid; i < SDN * TT; i += 256) {
        int c = i >> 5, tt = i & 31;
        int j = j0 + tt;
        float v = 0.f;
        if (j < FOUT) v = sp[(size_t)c * FOUT + j];
        tile[i] = fmaxf(v, 0.f);
    }
    __syncthreads();

    float* hp = h1 + (size_t)b * SDN * FOUT;
    for (int g = 0; g < 2; g++) {
        int o = tid + g * 256;
        float acc[TT];
#pragma unroll
        for (int k = 0; k < TT; k++) acc[k] = 0.f;
        for (int c = 0; c < SDN; c++) {
            float w = W[c * SDN + o];
            const float4* v = reinterpret_cast<const float4*>(tile + c * TT);
#pragma unroll
            for (int k = 0; k < TT / 4; k++) {
                float4 a = v[k];
                acc[4*k+0] = fmaf(w, a.x, acc[4*k+0]);
                acc[4*k+1] = fmaf(w, a.y, acc[4*k+1]);
                acc[4*k+2] = fmaf(w, a.z, acc[4*k+2]);
                acc[4*k+3] = fmaf(w, a.w, acc[4*k+3]);
            }
        }
#pragma unroll
        for (int k = 0; k < TT; k++) stg[tid * TT + k] = fmaxf(acc[k], 0.f);
        __syncthreads();
        for (int i = tid; i < 256 * TT; i += 256) {
            int oo = (i >> 5) + g * 256, tt = i & 31;
            int j = j0 + tt;
            if (j < FOUT) hp[(size_t)oo * FOUT + j] = stg[i];
        }
        __syncthreads();
    }
}

// out[b][o][j] = sum_c h1[b][c][j] * W[c*256+o]
__global__ void __launch_bounds__(256)
post2_kernel(const float* __restrict__ h1,
             float* __restrict__ out,
             const float* __restrict__ W) {
    extern __shared__ float sm[];
    float* tile = sm;             // [512][32]
    float* stg  = sm + SDN * TT;  // [256][32]
    const int b = blockIdx.y;
    const int j0 = blockIdx.x * TT;
    const int tid = threadIdx.x;

    const float* hp = h1 + (size_t)b * SDN * FOUT;
    for (int i = tid; i < SDN * TT; i += 256) {
        int c = i >> 5, tt = i & 31;
        int j = j0 + tt;
        tile[i] = (j < FOUT) ? hp[(size_t)c * FOUT + j] : 0.f;
    }
    __syncthreads();

    {
        int o = tid;
        float acc[TT];
#pragma unroll
        for (int k = 0; k < TT; k++) acc[k] = 0.f;
        for (int c = 0; c < SDN; c++) {
            float w = W[c * 256 + o];
            const float4* v = reinterpret_cast<const float4*>(tile + c * TT);
#pragma unroll
            for (int k = 0; k < TT / 4; k++) {
                float4 a = v[k];
                acc[4*k+0] = fmaf(w, a.x, acc[4*k+0]);
                acc[4*k+1] = fmaf(w, a.y, acc[4*k+1]);
                acc[4*k+2] = fmaf(w, a.z, acc[4*k+2]);
                acc[4*k+3] = fmaf(w, a.w, acc[4*k+3]);
            }
        }
#pragma unroll
        for (int k = 0; k < TT; k++) stg[tid * TT + k] = acc[k];
    }
    __syncthreads();
    float* ob = out + (size_t)b * 256 * FOUT;
    for (int i = tid; i < 256 * TT; i += 256) {
        int oo = i >> 5, tt = i & 31;
        int j = j0 + tt;
        if (j < FOUT) ob[(size_t)oo * FOUT + j] = stg[i];
    }
}

extern "C" void kernel_launch(void* const* d_in, const int* in_sizes, int n_in,
                              void* d_out, int out_size) {
    const int*   y   = (const int*)d_in[0];
    const float* emb = (const float*)d_in[1];
    const float* Wd  = (const float*)d_in[2];
    const float* bd  = (const float*)d_in[3];
    const float* Wr  = (const float*)d_in[4];
    const float* br  = (const float*)d_in[5];
    const float* Ws  = (const float*)d_in[6];
    const float* bs  = (const float*)d_in[7];
    const float* p1  = (const float*)d_in[8];
    const float* p2  = (const float*)d_in[9];
    float* out = (float*)d_out;

    float *xA, *xB, *skip, *h1;
    cudaGetSymbolAddress((void**)&xA,   g_xA);
    cudaGetSymbolAddress((void**)&xB,   g_xB);
    cudaGetSymbolAddress((void**)&skip, g_skip);
    cudaGetSymbolAddress((void**)&h1,   g_h1);

    const int layerSmem = 3 * 128 * XS * 4;            // 54 KB
    const int postSmem  = (SDN * TT + 256 * TT) * 4;   // 96 KB
    cudaFuncSetAttribute(layer_kernel, cudaFuncAttributeMaxDynamicSharedMemorySize, layerSmem);
    cudaFuncSetAttribute(post1_kernel, cudaFuncAttributeMaxDynamicSharedMemorySize, postSmem);
    cudaFuncSetAttribute(post2_kernel, cudaFuncAttributeMaxDynamicSharedMemorySize, postSmem);

    zero_kernel<<<512, 256>>>(skip, BN * SDN * FOUT);
    embed_kernel<<<2048, 256>>>(y, emb, xA);

    static const int dil[20] = {1, 2, 4, 8, 16, 32, 64, 128, 256, 512,
                                1, 2, 4, 8, 16, 32, 64, 128, 256, 512};
    int off = 0;
    float* cur = xA;
    float* nxt = xB;
    for (int i = 0; i < 20; i++) {
        int d = dil[i];
        int tstart = off + d;
        int len = TN - tstart;
        int tiles = (len + TT - 1) / TT;
        layer_kernel<<<dim3(tiles, BN), 256, layerSmem>>>(
            cur, nxt, skip,
            Wd + (size_t)i * 2 * WDN * (2 * WDN),
            bd + (size_t)i * 2 * WDN,
            Wr + (size_t)i * WDN * WDN,
            br + (size_t)i * WDN,
            Ws + (size_t)i * WDN * SDN,
            bs + (size_t)i * SDN,
            d, tstart);
        float* tmp = cur; cur = nxt; nxt = tmp;
        off += d;
    }

    int jt = (FOUT + TT - 1) / TT;  // 193
    post1_kernel<<<dim3(jt, BN), 256, postSmem>>>(skip, h1, p1);
    post2_kernel<<<dim3(jt, BN), 256, postSmem>>>(h1, out, p2);
}

// round 15
// speedup vs baseline: 1.5693x; 1.0844x over previous
#include <cuda_runtime.h>
#include <math.h>

#define BN 8
#define TN 8192
#define WDN 128
#define SDN 512
#define FOUT 6145
#define SKIP0 2047   /* 8192 - 6145 */
#define TT 32
#define XS 36        /* padded stride for sDel/sCur/sAct (float4-aligned) */
#define CS 33        /* padded stride for staging */
#define NL 20

// Scratch (static device globals; no runtime allocation)
__device__ float g_xA[(size_t)BN * WDN * TN];
__device__ float g_xB[(size_t)BN * WDN * TN];
__device__ float g_skip[(size_t)BN * SDN * FOUT];
__device__ float g_h1[(size_t)BN * SDN * FOUT];
// Packed weights (filled per launch by pack kernels)
__device__ float4 g_w4d[(size_t)NL * 128 * 128];   // [l][c][o] = (w0a,w1a,w0g,w1g)
__device__ float4 g_wr4[(size_t)NL * 32 * 128];    // [l][c4][r] = Wr[4c4+j][r]
__device__ float4 g_ws4[(size_t)NL * 32 * 512];    // [l][c4][s] = Ws[4c4+j][s]

__device__ __forceinline__ float fast_tanh(float a) {
    float e = __expf(2.f * a);
    return 1.f - 2.f / (e + 1.f);
}
__device__ __forceinline__ float fast_sig(float g) {
    return 1.f / (1.f + __expf(-g));
}

__global__ void zero_kernel(float* __restrict__ p, int n) {
    for (int i = blockIdx.x * blockDim.x + threadIdx.x; i < n;
         i += gridDim.x * blockDim.x)
        p[i] = 0.f;
}

__global__ void embed_kernel(const int* __restrict__ y,
                             const float* __restrict__ emb,
                             float* __restrict__ x) {
    const int total = BN * WDN * TN;
    for (int i = blockIdx.x * blockDim.x + threadIdx.x; i < total;
         i += gridDim.x * blockDim.x) {
        int t = i & (TN - 1);
        int c = (i >> 13) & (WDN - 1);
        int b = i >> 20;
        x[i] = emb[y[b * TN + t] * WDN + c];
    }
}

// Pack Wd[l][h][c][o2] (o2 in 0..255) -> w4[l][c][o] = (h0/o, h1/o, h0/o+128, h1/o+128)
__global__ void pack_wd_kernel(const float* __restrict__ Wd, float4* __restrict__ w4) {
    const int total = NL * 128 * 128;
    for (int idx = blockIdx.x * blockDim.x + threadIdx.x; idx < total;
         idx += gridDim.x * blockDim.x) {
        int l = idx >> 14;
        int rem = idx & 16383;
        int c = rem >> 7, o = rem & 127;
        const float* base = Wd + (size_t)l * 65536;
        w4[idx] = make_float4(base[c * 256 + o],
                              base[(128 + c) * 256 + o],
                              base[c * 256 + o + 128],
                              base[(128 + c) * 256 + o + 128]);
    }
}

// Pack Wr[l][c][r] -> wr4[l][c4][r] = (c=4c4..4c4+3)
__global__ void pack_wr_kernel(const float* __restrict__ Wr, float4* __restrict__ w4) {
    const int total = NL * 32 * 128;
    for (int idx = blockIdx.x * blockDim.x + threadIdx.x; idx < total;
         idx += gridDim.x * blockDim.x) {
        int l = idx >> 12;
        int rem = idx & 4095;
        int c4 = rem >> 7, r = rem & 127;
        const float* base = Wr + (size_t)l * 16384;
        w4[idx] = make_float4(base[(4 * c4 + 0) * 128 + r],
                              base[(4 * c4 + 1) * 128 + r],
                              base[(4 * c4 + 2) * 128 + r],
                              base[(4 * c4 + 3) * 128 + r]);
    }
}

// Pack Ws[l][c][s] -> ws4[l][c4][s]
__global__ void pack_ws_kernel(const float* __restrict__ Ws, float4* __restrict__ w4) {
    const int total = NL * 32 * 512;
    for (int idx = blockIdx.x * blockDim.x + threadIdx.x; idx < total;
         idx += gridDim.x * blockDim.x) {
        int l = idx >> 14;
        int rem = idx & 16383;
        int c4 = rem >> 9, s = rem & 511;
        const float* base = Ws + (size_t)l * 65536;
        w4[idx] = make_float4(base[(4 * c4 + 0) * 512 + s],
                              base[(4 * c4 + 1) * 512 + s],
                              base[(4 * c4 + 2) * 512 + s],
                              base[(4 * c4 + 3) * 512 + s]);
    }
}

// Fused per-layer kernel. smem = 3 tiles * 128 * XS floats = 54KB -> 4 CTAs/SM.
__global__ void __launch_bounds__(256, 4)
layer_kernel(const float* __restrict__ xin,
             float* __restrict__ xout,
             float* __restrict__ skip,
             const float4* __restrict__ w4d,
             const float* __restrict__ bd,
             const float4* __restrict__ wr4,
             const float* __restrict__ br,
             const float4* __restrict__ ws4,
             const float* __restrict__ bs,
             int d, int tstart) {
    extern __shared__ float sm[];
    float* sDel = sm;                  // [128][XS]  x[t-d]
    float* sCur = sm + 128 * XS;       // [128][XS]  x[t]
    float* sAct = sm + 2 * 128 * XS;   // [128][XS]  gated acts
    // resStage overlays sDel ([128][CS]); skip chunk overlays sDel+sCur ([256][CS])

    const int b   = blockIdx.y;
    const int t0  = tstart + blockIdx.x * TT;
    const int tid = threadIdx.x;
    const float* xb = xin + (size_t)b * WDN * TN;

    // 1. load tiles (coalesced in t)
    for (int i = tid; i < WDN * TT; i += 256) {
        int c = i >> 5, tt = i & 31;
        int t = t0 + tt;
        float vc = 0.f, vd = 0.f;
        if (t < TN) {
            vc = xb[c * TN + t];
            vd = xb[c * TN + t - d];
        }
        sCur[c * XS + tt] = vc;
        sDel[c * XS + tt] = vd;
    }
    __syncthreads();

    // 2. conv + gate fused: thread owns output pair (o, o+128), 16 t's.
    //    One coalesced LDG.128 per c (packed weights).
    {
        const int o  = tid & 127;
        const int th = (tid >> 7) * 16;
        float aA[16], aG[16];
#pragma unroll
        for (int k = 0; k < 16; k++) { aA[k] = 0.f; aG[k] = 0.f; }
        const float4* W4 = w4d + o;
#pragma unroll 2
        for (int c = 0; c < WDN; c++) {
            float4 w = W4[c * 128];    // (w0a, w1a, w0g, w1g)
            const float4* v0 = reinterpret_cast<const float4*>(sDel + c * XS + th);
            const float4* v1 = reinterpret_cast<const float4*>(sCur + c * XS + th);
#pragma unroll
            for (int k = 0; k < 4; k++) {
                float4 a = v0[k];
                float4 q = v1[k];
                aA[4*k+0] = fmaf(w.x, a.x, aA[4*k+0]); aA[4*k+0] = fmaf(w.y, q.x, aA[4*k+0]);
                aA[4*k+1] = fmaf(w.x, a.y, aA[4*k+1]); aA[4*k+1] = fmaf(w.y, q.y, aA[4*k+1]);
                aA[4*k+2] = fmaf(w.x, a.z, aA[4*k+2]); aA[4*k+2] = fmaf(w.y, q.z, aA[4*k+2]);
                aA[4*k+3] = fmaf(w.x, a.w, aA[4*k+3]); aA[4*k+3] = fmaf(w.y, q.w, aA[4*k+3]);
                aG[4*k+0] = fmaf(w.z, a.x, aG[4*k+0]); aG[4*k+0] = fmaf(w.w, q.x, aG[4*k+0]);
                aG[4*k+1] = fmaf(w.z, a.y, aG[4*k+1]); aG[4*k+1] = fmaf(w.w, q.y, aG[4*k+1]);
                aG[4*k+2] = fmaf(w.z, a.z, aG[4*k+2]); aG[4*k+2] = fmaf(w.w, q.z, aG[4*k+2]);
                aG[4*k+3] = fmaf(w.z, a.w, aG[4*k+3]); aG[4*k+3] = fmaf(w.w, q.w, aG[4*k+3]);
            }
        }
        float ba = bd[o], bg = bd[o + 128];
#pragma unroll
        for (int j = 0; j < 16; j++) {
            float av = aA[j] + ba;
            float gv = aG[j] + bg;
            sAct[o * XS + th + j] = fast_tanh(av) * fast_sig(gv);
        }
    }
    __syncthreads();

    // 3. residual GEMM -> resStage (overlays sDel). One LDG.128 per 4 c.
    {
        const int r  = tid & 127;
        const int tb = (tid >> 7) * 16;
        float acc[16];
#pragma unroll
        for (int k = 0; k < 16; k++) acc[k] = 0.f;
        const float4* WR = wr4 + r;
#pragma unroll 2
        for (int c4 = 0; c4 < 32; c4++) {
            float4 wv = WR[c4 * 128];
            float wj[4] = {wv.x, wv.y, wv.z, wv.w};
#pragma unroll
            for (int j = 0; j < 4; j++) {
                float w = wj[j];
                const float4* v = reinterpret_cast<const float4*>(sAct + (4 * c4 + j) * XS + tb);
#pragma unroll
                for (int k = 0; k < 4; k++) {
                    float4 a = v[k];
                    acc[4*k+0] = fmaf(w, a.x, acc[4*k+0]);
                    acc[4*k+1] = fmaf(w, a.y, acc[4*k+1]);
                    acc[4*k+2] = fmaf(w, a.z, acc[4*k+2]);
                    acc[4*k+3] = fmaf(w, a.w, acc[4*k+3]);
                }
            }
        }
        float* resStage = sDel;
        float bias = br[r];
#pragma unroll
        for (int j = 0; j < 16; j++)
            resStage[r * CS + tb + j] = acc[j] + bias + sCur[r * XS + tb + j];
    }
    __syncthreads();

    // 4. write x_next (coalesced from resStage)
    {
        float* xob = xout + (size_t)b * WDN * TN;
        const float* resStage = sDel;
        for (int i = tid; i < WDN * TT; i += 256) {
            int c = i >> 5, tt = i & 31;
            int t = t0 + tt;
            if (t < TN) xob[c * TN + t] = resStage[c * CS + tt];
        }
    }

    // 5. skip GEMM in two 256-row passes. One LDG.128 per 4 c.
    if (t0 + TT > SKIP0) {
        float* chunk = sm;  // [256][CS]
        float* skb = skip + (size_t)b * SDN * FOUT;
#pragma unroll 1
        for (int p = 0; p < 2; p++) {
            __syncthreads();
            const int s = p * 256 + tid;
            float acc[TT];
#pragma unroll
            for (int k = 0; k < TT; k++) acc[k] = 0.f;
            const float4* WS = ws4 + s;
#pragma unroll 1
            for (int c4 = 0; c4 < 32; c4++) {
                float4 wv = WS[c4 * 512];
                float wj[4] = {wv.x, wv.y, wv.z, wv.w};
#pragma unroll
                for (int j = 0; j < 4; j++) {
                    float w = wj[j];
                    const float4* v = reinterpret_cast<const float4*>(sAct + (4 * c4 + j) * XS);
#pragma unroll
                    for (int k = 0; k < TT / 4; k++) {
                        float4 a = v[k];
                        acc[4*k+0] = fmaf(w, a.x, acc[4*k+0]);
                        acc[4*k+1] = fmaf(w, a.y, acc[4*k+1]);
                        acc[4*k+2] = fmaf(w, a.z, acc[4*k+2]);
                        acc[4*k+3] = fmaf(w, a.w, acc[4*k+3]);
                    }
                }
            }
            float bias = bs[s];
#pragma unroll
            for (int k = 0; k < TT; k++) chunk[tid * CS + k] = acc[k] + bias;
            __syncthreads();
            for (int i = tid; i < 256 * TT; i += 256) {
                int row = i >> 5, col = i & 31;
                int t = t0 + col;
                if (t >= SKIP0 && t < TN)
                    skb[(size_t)(p * 256 + row) * FOUT + (t - SKIP0)] += chunk[row * CS + col];
            }
        }
    }
}

// h1[b][o][j] = relu( sum_c relu(skip[b][c][j]) * W[c*512+o] )
__global__ void __launch_bounds__(256)
post1_kernel(const float* __restrict__ skip,
             float* __restrict__ h1,
             const float* __restrict__ W) {
    extern __shared__ float sm[];
    float* tile = sm;             // [512][32]
    float* stg  = sm + SDN * TT;  // [256][32]
    const int b = blockIdx.y;
    const int j0 = blockIdx.x * TT;
    const int tid = threadIdx.x;

    const float* sp = skip + (size_t)b * SDN * FOUT;
    for (int i = tid; i < SDN * TT; i += 256) {
        int c = i >> 5, tt = i & 31;
        int j = j0 + tt;
        float v = 0.f;
        if (j < FOUT) v = sp[(size_t)c * FOUT + j];
        tile[i] = fmaxf(v, 0.f);
    }
    __syncthreads();

    float* hp = h1 + (size_t)b * SDN * FOUT;
    for (int g = 0; g < 2; g++) {
        int o = tid + g * 256;
        float acc[TT];
#pragma unroll
        for (int k = 0; k < TT; k++) acc[k] = 0.f;
        for (int c = 0; c < SDN; c++) {
            float w = W[c * SDN + o];
            const float4* v = reinterpret_cast<const float4*>(tile + c * TT);
#pragma unroll
            for (int k = 0; k < TT / 4; k++) {
                float4 a = v[k];
                acc[4*k+0] = fmaf(w, a.x, acc[4*k+0]);
                acc[4*k+1] = fmaf(w, a.y, acc[4*k+1]);
                acc[4*k+2] = fmaf(w, a.z, acc[4*k+2]);
                acc[4*k+3] = fmaf(w, a.w, acc[4*k+3]);
            }
        }
#pragma unroll
        for (int k = 0; k < TT; k++) stg[tid * TT + k] = fmaxf(acc[k], 0.f);
        __syncthreads();
        for (int i = tid; i < 256 * TT; i += 256) {
            int oo = (i >> 5) + g * 256, tt = i & 31;
            int j = j0 + tt;
            if (j < FOUT) hp[(size_t)oo * FOUT + j] = stg[i];
        }
        __syncthreads();
    }
}

// out[b][o][j] = sum_c h1[b][c][j] * W[c*256+o]
__global__ void __launch_bounds__(256)
post2_kernel(const float* __restrict__ h1,
             float* __restrict__ out,
             const float* __restrict__ W) {
    extern __shared__ float sm[];
    float* tile = sm;             // [512][32]
    float* stg  = sm + SDN * TT;  // [256][32]
    const int b = blockIdx.y;
    const int j0 = blockIdx.x * TT;
    const int tid = threadIdx.x;

    const float* hp = h1 + (size_t)b * SDN * FOUT;
    for (int i = tid; i < SDN * TT; i += 256) {
        int c = i >> 5, tt = i & 31;
        int j = j0 + tt;
        tile[i] = (j < FOUT) ? hp[(size_t)c * FOUT + j] : 0.f;
    }
    __syncthreads();

    {
        int o = tid;
        float acc[TT];
#pragma unroll
        for (int k = 0; k < TT; k++) acc[k] = 0.f;
        for (int c = 0; c < SDN; c++) {
            float w = W[c * 256 + o];
            const float4* v = reinterpret_cast<const float4*>(tile + c * TT);
#pragma unroll
            for (int k = 0; k < TT / 4; k++) {
                float4 a = v[k];
                acc[4*k+0] = fmaf(w, a.x, acc[4*k+0]);
                acc[4*k+1] = fmaf(w, a.y, acc[4*k+1]);
                acc[4*k+2] = fmaf(w, a.z, acc[4*k+2]);
                acc[4*k+3] = fmaf(w, a.w, acc[4*k+3]);
            }
        }
#pragma unroll
        for (int k = 0; k < TT; k++) stg[tid * TT + k] = acc[k];
    }
    __syncthreads();
    float* ob = out + (size_t)b * 256 * FOUT;
    for (int i = tid; i < 256 * TT; i += 256) {
        int oo = i >> 5, tt = i & 31;
        int j = j0 + tt;
        if (j < FOUT) ob[(size_t)oo * FOUT + j] = stg[i];
    }
}

extern "C" void kernel_launch(void* const* d_in, const int* in_sizes, int n_in,
                              void* d_out, int out_size) {
    const int*   y   = (const int*)d_in[0];
    const float* emb = (const float*)d_in[1];
    const float* Wd  = (const float*)d_in[2];
    const float* bd  = (const float*)d_in[3];
    const float* Wr  = (const float*)d_in[4];
    const float* br  = (const float*)d_in[5];
    const float* Ws  = (const float*)d_in[6];
    const float* bs  = (const float*)d_in[7];
    const float* p1  = (const float*)d_in[8];
    const float* p2  = (const float*)d_in[9];
    float* out = (float*)d_out;

    float *xA, *xB, *skip, *h1;
    float4 *w4d, *wr4, *ws4;
    cudaGetSymbolAddress((void**)&xA,   g_xA);
    cudaGetSymbolAddress((void**)&xB,   g_xB);
    cudaGetSymbolAddress((void**)&skip, g_skip);
    cudaGetSymbolAddress((void**)&h1,   g_h1);
    cudaGetSymbolAddress((void**)&w4d,  g_w4d);
    cudaGetSymbolAddress((void**)&wr4,  g_wr4);
    cudaGetSymbolAddress((void**)&ws4,  g_ws4);

    const int layerSmem = 3 * 128 * XS * 4;            // 54 KB
    const int postSmem  = (SDN * TT + 256 * TT) * 4;   // 96 KB
    cudaFuncSetAttribute(layer_kernel, cudaFuncAttributeMaxDynamicSharedMemorySize, layerSmem);
    cudaFuncSetAttribute(post1_kernel, cudaFuncAttributeMaxDynamicSharedMemorySize, postSmem);
    cudaFuncSetAttribute(post2_kernel, cudaFuncAttributeMaxDynamicSharedMemorySize, postSmem);

    zero_kernel<<<512, 256>>>(skip, BN * SDN * FOUT);
    embed_kernel<<<2048, 256>>>(y, emb, xA);
    pack_wd_kernel<<<320, 256>>>(Wd, w4d);
    pack_wr_kernel<<<80, 256>>>(Wr, wr4);
    pack_ws_kernel<<<320, 256>>>(Ws, ws4);

    static const int dil[20] = {1, 2, 4, 8, 16, 32, 64, 128, 256, 512,
                                1, 2, 4, 8, 16, 32, 64, 128, 256, 512};
    int off = 0;
    float* cur = xA;
    float* nxt = xB;
    for (int i = 0; i < 20; i++) {
        int d = dil[i];
        int tstart = off + d;
        int len = TN - tstart;
        int tiles = (len + TT - 1) / TT;
        layer_kernel<<<dim3(tiles, BN), 256, layerSmem>>>(
            cur, nxt, skip,
            w4d + (size_t)i * 128 * 128,
            bd + (size_t)i * 2 * WDN,
            wr4 + (size_t)i * 32 * 128,
            br + (size_t)i * WDN,
            ws4 + (size_t)i * 32 * 512,
            bs + (size_t)i * SDN,
            d, tstart);
        float* tmp = cur; cur = nxt; nxt = tmp;
        off += d;
    }

    int jt = (FOUT + TT - 1) / TT;  // 193
    post1_kernel<<<dim3(jt, BN), 256, postSmem>>>(skip, h1, p1);
    post2_kernel<<<dim3(jt, BN), 256, postSmem>>>(h1, out, p2);
}

// round 16
// speedup vs baseline: 1.6715x; 1.0651x over previous
#include <cuda_runtime.h>
#include <math.h>

#define BN 8
#define TN 8192
#define WDN 128
#define SDN 512
#define FOUT 6145
#define SKIP0 2047   /* 8192 - 6145 */
#define TT 32
#define XS 36        /* padded stride for sDel/sCur/sAct (float4-aligned) */
#define CS 33        /* padded stride for staging */
#define NL 20

// Scratch (static device globals; no runtime allocation)
__device__ float g_xA[(size_t)BN * WDN * TN];
__device__ float g_xB[(size_t)BN * WDN * TN];
__device__ float g_skip[(size_t)BN * SDN * FOUT];
__device__ float g_h1[(size_t)BN * SDN * FOUT];
// Packed weights (filled per launch by pack kernels)
__device__ float4 g_w4d[(size_t)NL * 128 * 128];   // [l][c][o] = (w0a,w1a,w0g,w1g)
__device__ float4 g_wr4[(size_t)NL * 32 * 128];    // [l][c4][r] = Wr[4c4+j][r]
__device__ float4 g_ws4[(size_t)NL * 32 * 512];    // [l][c4][s] = Ws[4c4+j][s]

typedef unsigned long long u64;

// ---- f32x2 packed-FMA helpers (Blackwell FFMA2; bit-identical to 2x fmaf) ----
__device__ __forceinline__ u64 pack2(float lo, float hi) {
    u64 r;
    asm("mov.b64 %0, {%1, %2};" : "=l"(r) : "f"(lo), "f"(hi));
    return r;
}
__device__ __forceinline__ u64 dup2(float v) { return pack2(v, v); }
__device__ __forceinline__ void unpack2(u64 v, float& lo, float& hi) {
    asm("mov.b64 {%0, %1}, %2;" : "=f"(lo), "=f"(hi) : "l"(v));
}
#define FMA2(acc, a, b) \
    asm("fma.rn.f32x2 %0, %1, %2, %0;" : "+l"(acc) : "l"(a), "l"(b))

__device__ __forceinline__ float fast_tanh(float a) {
    float e = __expf(2.f * a);
    return 1.f - 2.f / (e + 1.f);
}
__device__ __forceinline__ float fast_sig(float g) {
    return 1.f / (1.f + __expf(-g));
}

__global__ void zero_kernel(float* __restrict__ p, int n) {
    for (int i = blockIdx.x * blockDim.x + threadIdx.x; i < n;
         i += gridDim.x * blockDim.x)
        p[i] = 0.f;
}

__global__ void embed_kernel(const int* __restrict__ y,
                             const float* __restrict__ emb,
                             float* __restrict__ x) {
    const int total = BN * WDN * TN;
    for (int i = blockIdx.x * blockDim.x + threadIdx.x; i < total;
         i += gridDim.x * blockDim.x) {
        int t = i & (TN - 1);
        int c = (i >> 13) & (WDN - 1);
        int b = i >> 20;
        x[i] = emb[y[b * TN + t] * WDN + c];
    }
}

__global__ void pack_wd_kernel(const float* __restrict__ Wd, float4* __restrict__ w4) {
    const int total = NL * 128 * 128;
    for (int idx = blockIdx.x * blockDim.x + threadIdx.x; idx < total;
         idx += gridDim.x * blockDim.x) {
        int l = idx >> 14;
        int rem = idx & 16383;
        int c = rem >> 7, o = rem & 127;
        const float* base = Wd + (size_t)l * 65536;
        w4[idx] = make_float4(base[c * 256 + o],
                              base[(128 + c) * 256 + o],
                              base[c * 256 + o + 128],
                              base[(128 + c) * 256 + o + 128]);
    }
}

__global__ void pack_wr_kernel(const float* __restrict__ Wr, float4* __restrict__ w4) {
    const int total = NL * 32 * 128;
    for (int idx = blockIdx.x * blockDim.x + threadIdx.x; idx < total;
         idx += gridDim.x * blockDim.x) {
        int l = idx >> 12;
        int rem = idx & 4095;
        int c4 = rem >> 7, r = rem & 127;
        const float* base = Wr + (size_t)l * 16384;
        w4[idx] = make_float4(base[(4 * c4 + 0) * 128 + r],
                              base[(4 * c4 + 1) * 128 + r],
                              base[(4 * c4 + 2) * 128 + r],
                              base[(4 * c4 + 3) * 128 + r]);
    }
}

__global__ void pack_ws_kernel(const float* __restrict__ Ws, float4* __restrict__ w4) {
    const int total = NL * 32 * 512;
    for (int idx = blockIdx.x * blockDim.x + threadIdx.x; idx < total;
         idx += gridDim.x * blockDim.x) {
        int l = idx >> 14;
        int rem = idx & 16383;
        int c4 = rem >> 9, s = rem & 511;
        const float* base = Ws + (size_t)l * 65536;
        w4[idx] = make_float4(base[(4 * c4 + 0) * 512 + s],
                              base[(4 * c4 + 1) * 512 + s],
                              base[(4 * c4 + 2) * 512 + s],
                              base[(4 * c4 + 3) * 512 + s]);
    }
}

// Fused per-layer kernel. smem = 3 tiles * 128 * XS floats = 54KB -> 4 CTAs/SM.
__global__ void __launch_bounds__(256, 4)
layer_kernel(const float* __restrict__ xin,
             float* __restrict__ xout,
             float* __restrict__ skip,
             const float4* __restrict__ w4d,
             const float* __restrict__ bd,
             const float4* __restrict__ wr4,
             const float* __restrict__ br,
             const float4* __restrict__ ws4,
             const float* __restrict__ bs,
             int d, int tstart) {
    extern __shared__ float sm[];
    float* sDel = sm;                  // [128][XS]  x[t-d]
    float* sCur = sm + 128 * XS;       // [128][XS]  x[t]
    float* sAct = sm + 2 * 128 * XS;   // [128][XS]  gated acts
    // resStage overlays sDel ([128][CS]); skip chunk overlays sDel+sCur ([256][CS])

    const int b   = blockIdx.y;
    const int t0  = tstart + blockIdx.x * TT;
    const int tid = threadIdx.x;
    const float* xb = xin + (size_t)b * WDN * TN;

    // 1. load tiles (coalesced in t)
    for (int i = tid; i < WDN * TT; i += 256) {
        int c = i >> 5, tt = i & 31;
        int t = t0 + tt;
        float vc = 0.f, vd = 0.f;
        if (t < TN) {
            vc = xb[c * TN + t];
            vd = xb[c * TN + t - d];
        }
        sCur[c * XS + tt] = vc;
        sDel[c * XS + tt] = vd;
    }
    __syncthreads();

    // 2. conv + gate fused. One LDG.128 weight per c; 32 FFMA2 per c.
    {
        const int o  = tid & 127;
        const int th = (tid >> 7) * 16;
        u64 aA[8], aG[8];
#pragma unroll
        for (int k = 0; k < 8; k++) { aA[k] = 0ull; aG[k] = 0ull; }
        const float4* W4 = w4d + o;
#pragma unroll 2
        for (int c = 0; c < WDN; c++) {
            float4 w = W4[c * 128];    // (w0a, w1a, w0g, w1g)
            u64 w0a = dup2(w.x), w1a = dup2(w.y);
            u64 w0g = dup2(w.z), w1g = dup2(w.w);
            const ulonglong2* v0 = reinterpret_cast<const ulonglong2*>(sDel + c * XS + th);
            const ulonglong2* v1 = reinterpret_cast<const ulonglong2*>(sCur + c * XS + th);
#pragma unroll
            for (int k = 0; k < 4; k++) {    // 4 x 16B = 16 t's
                ulonglong2 a = v0[k];
                ulonglong2 q = v1[k];
                FMA2(aA[2*k],   w0a, a.x); FMA2(aA[2*k],   w1a, q.x);
                FMA2(aA[2*k+1], w0a, a.y); FMA2(aA[2*k+1], w1a, q.y);
                FMA2(aG[2*k],   w0g, a.x); FMA2(aG[2*k],   w1g, q.x);
                FMA2(aG[2*k+1], w0g, a.y); FMA2(aG[2*k+1], w1g, q.y);
            }
        }
        float ba = bd[o], bg = bd[o + 128];
#pragma unroll
        for (int j = 0; j < 8; j++) {
            float a0, a1, g0, g1;
            unpack2(aA[j], a0, a1);
            unpack2(aG[j], g0, g1);
            sAct[o * XS + th + 2*j]     = fast_tanh(a0 + ba) * fast_sig(g0 + bg);
            sAct[o * XS + th + 2*j + 1] = fast_tanh(a1 + ba) * fast_sig(g1 + bg);
        }
    }
    __syncthreads();

    // 3. residual GEMM -> resStage (overlays sDel). 32 FFMA2 per c4.
    {
        const int r  = tid & 127;
        const int tb = (tid >> 7) * 16;
        u64 acc[8];
#pragma unroll
        for (int k = 0; k < 8; k++) acc[k] = 0ull;
        const float4* WR = wr4 + r;
#pragma unroll 2
        for (int c4 = 0; c4 < 32; c4++) {
            float4 wv = WR[c4 * 128];
            u64 w2[4] = {dup2(wv.x), dup2(wv.y), dup2(wv.z), dup2(wv.w)};
#pragma unroll
            for (int j = 0; j < 4; j++) {
                const ulonglong2* v =
                    reinterpret_cast<const ulonglong2*>(sAct + (4 * c4 + j) * XS + tb);
#pragma unroll
                for (int k = 0; k < 4; k++) {
                    ulonglong2 a = v[k];
                    FMA2(acc[2*k],   w2[j], a.x);
                    FMA2(acc[2*k+1], w2[j], a.y);
                }
            }
        }
        float* resStage = sDel;
        float bias = br[r];
#pragma unroll
        for (int j = 0; j < 8; j++) {
            float a0, a1;
            unpack2(acc[j], a0, a1);
            resStage[r * CS + tb + 2*j]     = a0 + bias + sCur[r * XS + tb + 2*j];
            resStage[r * CS + tb + 2*j + 1] = a1 + bias + sCur[r * XS + tb + 2*j + 1];
        }
    }
    __syncthreads();

    // 4. write x_next (coalesced from resStage)
    {
        float* xob = xout + (size_t)b * WDN * TN;
        const float* resStage = sDel;
        for (int i = tid; i < WDN * TT; i += 256) {
            int c = i >> 5, tt = i & 31;
            int t = t0 + tt;
            if (t < TN) xob[c * TN + t] = resStage[c * CS + tt];
        }
    }

    // 5. skip GEMM in two 256-row passes. 64 FFMA2 per c4.
    if (t0 + TT > SKIP0) {
        float* chunk = sm;  // [256][CS]
        float* skb = skip + (size_t)b * SDN * FOUT;
#pragma unroll 1
        for (int p = 0; p < 2; p++) {
            __syncthreads();
            const int s = p * 256 + tid;
            u64 acc[16];
#pragma unroll
            for (int k = 0; k < 16; k++) acc[k] = 0ull;
            const float4* WS = ws4 + s;
#pragma unroll 1
            for (int c4 = 0; c4 < 32; c4++) {
                float4 wv = WS[c4 * 512];
                u64 w2[4] = {dup2(wv.x), dup2(wv.y), dup2(wv.z), dup2(wv.w)};
#pragma unroll
                for (int j = 0; j < 4; j++) {
                    const ulonglong2* v =
                        reinterpret_cast<const ulonglong2*>(sAct + (4 * c4 + j) * XS);
#pragma unroll
                    for (int k = 0; k < 8; k++) {   // 32 t's
                        ulonglong2 a = v[k];
                        FMA2(acc[2*k],   w2[j], a.x);
                        FMA2(acc[2*k+1], w2[j], a.y);
                    }
                }
            }
            float bias = bs[s];
#pragma unroll
            for (int k = 0; k < 16; k++) {
                float a0, a1;
                unpack2(acc[k], a0, a1);
                chunk[tid * CS + 2*k]     = a0 + bias;
                chunk[tid * CS + 2*k + 1] = a1 + bias;
            }
            __syncthreads();
            for (int i = tid; i < 256 * TT; i += 256) {
                int row = i >> 5, col = i & 31;
                int t = t0 + col;
                if (t >= SKIP0 && t < TN)
                    skb[(size_t)(p * 256 + row) * FOUT + (t - SKIP0)] += chunk[row * CS + col];
            }
        }
    }
}

// h1[b][o][j] = relu( sum_c relu(skip[b][c][j]) * W[c*512+o] )
__global__ void __launch_bounds__(256)
post1_kernel(const float* __restrict__ skip,
             float* __restrict__ h1,
             const float* __restrict__ W) {
    extern __shared__ float sm[];
    float* tile = sm;             // [512][32]
    float* stg  = sm + SDN * TT;  // [256][32]
    const int b = blockIdx.y;
    const int j0 = blockIdx.x * TT;
    const int tid = threadIdx.x;

    const float* sp = skip + (size_t)b * SDN * FOUT;
    for (int i = tid; i < SDN * TT; i += 256) {
        int c = i >> 5, tt = i & 31;
        int j = j0 + tt;
        float v = 0.f;
        if (j < FOUT) v = sp[(size_t)c * FOUT + j];
        tile[i] = fmaxf(v, 0.f);
    }
    __syncthreads();

    float* hp = h1 + (size_t)b * SDN * FOUT;
    for (int g = 0; g < 2; g++) {
        int o = tid + g * 256;
        u64 acc[16];
#pragma unroll
        for (int k = 0; k < 16; k++) acc[k] = 0ull;
        for (int c = 0; c < SDN; c++) {
            u64 w = dup2(W[c * SDN + o]);
            const ulonglong2* v = reinterpret_cast<const ulonglong2*>(tile + c * TT);
#pragma unroll
            for (int k = 0; k < 8; k++) {
                ulonglong2 a = v[k];
                FMA2(acc[2*k],   w, a.x);
                FMA2(acc[2*k+1], w, a.y);
            }
        }
#pragma unroll
        for (int k = 0; k < 16; k++) {
            float a0, a1;
            unpack2(acc[k], a0, a1);
            stg[tid * TT + 2*k]     = fmaxf(a0, 0.f);
            stg[tid * TT + 2*k + 1] = fmaxf(a1, 0.f);
        }
        __syncthreads();
        for (int i = tid; i < 256 * TT; i += 256) {
            int oo = (i >> 5) + g * 256, tt = i & 31;
            int j = j0 + tt;
            if (j < FOUT) hp[(size_t)oo * FOUT + j] = stg[i];
        }
        __syncthreads();
    }
}

// out[b][o][j] = sum_c h1[b][c][j] * W[c*256+o]
__global__ void __launch_bounds__(256)
post2_kernel(const float* __restrict__ h1,
             float* __restrict__ out,
             const float* __restrict__ W) {
    extern __shared__ float sm[];
    float* tile = sm;             // [512][32]
    float* stg  = sm + SDN * TT;  // [256][32]
    const int b = blockIdx.y;
    const int j0 = blockIdx.x * TT;
    const int tid = threadIdx.x;

    const float* hp = h1 + (size_t)b * SDN * FOUT;
    for (int i = tid; i < SDN * TT; i += 256) {
        int c = i >> 5, tt = i & 31;
        int j = j0 + tt;
        tile[i] = (j < FOUT) ? hp[(size_t)c * FOUT + j] : 0.f;
    }
    __syncthreads();

    {
        int o = tid;
        u64 acc[16];
#pragma unroll
        for (int k = 0; k < 16; k++) acc[k] = 0ull;
        for (int c = 0; c < SDN; c++) {
            u64 w = dup2(W[c * 256 + o]);
            const ulonglong2* v = reinterpret_cast<const ulonglong2*>(tile + c * TT);
#pragma unroll
            for (int k = 0; k < 8; k++) {
                ulonglong2 a = v[k];
                FMA2(acc[2*k],   w, a.x);
                FMA2(acc[2*k+1], w, a.y);
            }
        }
#pragma unroll
        for (int k = 0; k < 16; k++) {
            float a0, a1;
            unpack2(acc[k], a0, a1);
            stg[tid * TT + 2*k]     = a0;
            stg[tid * TT + 2*k + 1] = a1;
        }
    }
    __syncthreads();
    float* ob = out + (size_t)b * 256 * FOUT;
    for (int i = tid; i < 256 * TT; i += 256) {
        int oo = i >> 5, tt = i & 31;
        int j = j0 + tt;
        if (j < FOUT) ob[(size_t)oo * FOUT + j] = stg[i];
    }
}

extern "C" void kernel_launch(void* const* d_in, const int* in_sizes, int n_in,
                              void* d_out, int out_size) {
    const int*   y   = (const int*)d_in[0];
    const float* emb = (const float*)d_in[1];
    const float* Wd  = (const float*)d_in[2];
    const float* bd  = (const float*)d_in[3];
    const float* Wr  = (const float*)d_in[4];
    const float* br  = (const float*)d_in[5];
    const float* Ws  = (const float*)d_in[6];
    const float* bs  = (const float*)d_in[7];
    const float* p1  = (const float*)d_in[8];
    const float* p2  = (const float*)d_in[9];
    float* out = (float*)d_out;

    float *xA, *xB, *skip, *h1;
    float4 *w4d, *wr4, *ws4;
    cudaGetSymbolAddress((void**)&xA,   g_xA);
    cudaGetSymbolAddress((void**)&xB,   g_xB);
    cudaGetSymbolAddress((void**)&skip, g_skip);
    cudaGetSymbolAddress((void**)&h1,   g_h1);
    cudaGetSymbolAddress((void**)&w4d,  g_w4d);
    cudaGetSymbolAddress((void**)&wr4,  g_wr4);
    cudaGetSymbolAddress((void**)&ws4,  g_ws4);

    const int layerSmem = 3 * 128 * XS * 4;            // 54 KB
    const int postSmem  = (SDN * TT + 256 * TT) * 4;   // 96 KB
    cudaFuncSetAttribute(layer_kernel, cudaFuncAttributeMaxDynamicSharedMemorySize, layerSmem);
    cudaFuncSetAttribute(post1_kernel, cudaFuncAttributeMaxDynamicSharedMemorySize, postSmem);
    cudaFuncSetAttribute(post2_kernel, cudaFuncAttributeMaxDynamicSharedMemorySize, postSmem);

    zero_kernel<<<512, 256>>>(skip, BN * SDN * FOUT);
    embed_kernel<<<2048, 256>>>(y, emb, xA);
    pack_wd_kernel<<<320, 256>>>(Wd, w4d);
    pack_wr_kernel<<<80, 256>>>(Wr, wr4);
    pack_ws_kernel<<<320, 256>>>(Ws, ws4);

    static const int dil[20] = {1, 2, 4, 8, 16, 32, 64, 128, 256, 512,
                                1, 2, 4, 8, 16, 32, 64, 128, 256, 512};
    int off = 0;
    float* cur = xA;
    float* nxt = xB;
    for (int i = 0; i < 20; i++) {
        int d = dil[i];
        int tstart = off + d;
        int len = TN - tstart;
        int tiles = (len + TT - 1) / TT;
        layer_kernel<<<dim3(tiles, BN), 256, layerSmem>>>(
            cur, nxt, skip,
            w4d + (size_t)i * 128 * 128,
            bd + (size_t)i * 2 * WDN,
            wr4 + (size_t)i * 32 * 128,
            br + (size_t)i * WDN,
            ws4 + (size_t)i * 32 * 512,
            bs + (size_t)i * SDN,
            d, tstart);
        float* tmp = cur; cur = nxt; nxt = tmp;
        off += d;
    }

    int jt = (FOUT + TT - 1) / TT;  // 193
    post1_kernel<<<dim3(jt, BN), 256, postSmem>>>(skip, h1, p1);
    post2_kernel<<<dim3(jt, BN), 256, postSmem>>>(h1, out, p2);
}